// round 1
// baseline (speedup 1.0000x reference)
#include <cuda_runtime.h>
#include <cuda_fp16.h>
#include <cstdint>

// Problem constants
constexpr int CB  = 4;
constexpr int CLQ = 4096;
constexpr int CLK = 4096;
constexpr int CD  = 256;

constexpr int QT = 128;       // q rows per CTA
constexpr int KT = 64;        // kv rows per tile
constexpr int STRIDE = 264;   // smem row stride in halfs (256 + 8 to dodge bank conflicts)
constexpr int NTHREADS = 256; // 8 warps

constexpr float SCALE   = 0.0625f;              // 256^-0.5
constexpr float NEG_BIG = -1000000000.0f;       // NEG_INF from reference
constexpr float LOG2E   = 1.4426950408889634f;
constexpr float MINIT   = -3.0e38f;             // finite "minus infinity" for running max

// fp16 copies of k and v (static device scratch; no allocation)
__device__ __half g_kh[(size_t)CB * CLK * CD];
__device__ __half g_vh[(size_t)CB * CLK * CD];

// ---------------------------------------------------------------------------
// k/v fp32 -> fp16 conversion
// ---------------------------------------------------------------------------
__global__ void convert_kv_kernel(const float* __restrict__ k, const float* __restrict__ v) {
    size_t i = (size_t)blockIdx.x * blockDim.x + threadIdx.x;
    size_t n4 = (size_t)CB * CLK * CD / 4;
    if (i >= n4) return;
    float4 a = reinterpret_cast<const float4*>(k)[i];
    float4 b = reinterpret_cast<const float4*>(v)[i];
    __half2* kh2 = reinterpret_cast<__half2*>(g_kh);
    __half2* vh2 = reinterpret_cast<__half2*>(g_vh);
    kh2[2 * i]     = __floats2half2_rn(a.x, a.y);
    kh2[2 * i + 1] = __floats2half2_rn(a.z, a.w);
    vh2[2 * i]     = __floats2half2_rn(b.x, b.y);
    vh2[2 * i + 1] = __floats2half2_rn(b.z, b.w);
}

// ---------------------------------------------------------------------------
// helpers
// ---------------------------------------------------------------------------
__device__ __forceinline__ float fast_ex2(float x) {
    float r;
    asm("ex2.approx.ftz.f32 %0, %1;" : "=f"(r) : "f"(x));
    return r;
}

__device__ __forceinline__ void ldm4(uint32_t& r0, uint32_t& r1, uint32_t& r2, uint32_t& r3, uint32_t a) {
    asm volatile("ldmatrix.sync.aligned.m8n8.x4.shared.b16 {%0,%1,%2,%3}, [%4];"
                 : "=r"(r0), "=r"(r1), "=r"(r2), "=r"(r3) : "r"(a));
}
__device__ __forceinline__ void ldm4t(uint32_t& r0, uint32_t& r1, uint32_t& r2, uint32_t& r3, uint32_t a) {
    asm volatile("ldmatrix.sync.aligned.m8n8.x4.trans.shared.b16 {%0,%1,%2,%3}, [%4];"
                 : "=r"(r0), "=r"(r1), "=r"(r2), "=r"(r3) : "r"(a));
}
__device__ __forceinline__ void mma16816(float* c, uint32_t a0, uint32_t a1, uint32_t a2, uint32_t a3,
                                         uint32_t b0, uint32_t b1) {
    asm volatile("mma.sync.aligned.m16n8k16.row.col.f32.f16.f16.f32 "
                 "{%0,%1,%2,%3}, {%4,%5,%6,%7}, {%8,%9}, {%0,%1,%2,%3};"
                 : "+f"(c[0]), "+f"(c[1]), "+f"(c[2]), "+f"(c[3])
                 : "r"(a0), "r"(a1), "r"(a2), "r"(a3), "r"(b0), "r"(b1));
}
__device__ __forceinline__ uint32_t h2u(__half2 h) {
    return *reinterpret_cast<uint32_t*>(&h);
}

// S = qw (sQ) @ k^T (sK), 16 rows per warp x 64 kv cols, k-dim = 256
__device__ __forceinline__ void compute_S(float (&sacc)[8][4], uint32_t aBase, uint32_t bBaseK) {
#pragma unroll
    for (int i = 0; i < 8; i++)
#pragma unroll
        for (int j = 0; j < 4; j++) sacc[i][j] = 0.f;
#pragma unroll
    for (int kc = 0; kc < 16; kc++) {
        uint32_t a0, a1, a2, a3;
        ldm4(a0, a1, a2, a3, aBase + (uint32_t)(kc * 16 * 2));
#pragma unroll
        for (int nt2 = 0; nt2 < 4; nt2++) {
            uint32_t b0, b1, b2, b3;
            ldm4(b0, b1, b2, b3, bBaseK + (uint32_t)((nt2 * 16 * STRIDE + kc * 16) * 2));
            mma16816(sacc[nt2 * 2],     a0, a1, a2, a3, b0, b1);
            mma16816(sacc[nt2 * 2 + 1], a0, a1, a2, a3, b2, b3);
        }
    }
}

// ---------------------------------------------------------------------------
// fused attention kernel: qw gemm + 2-pass flash softmax + att write + PV
// grid = (LQ/QT, B), 256 threads
// ---------------------------------------------------------------------------
extern __shared__ __half smem_h[];

__global__ void __launch_bounds__(NTHREADS, 1)
attn_kernel(const float* __restrict__ q, const float* __restrict__ w,
            const int* __restrict__ kidx, float* __restrict__ out, float* __restrict__ att) {
    __half* sQ = smem_h;                  // QT x STRIDE (q fp16, then qw fp16)
    __half* sK = sQ + QT * STRIDE;        // KT x STRIDE (w chunk / k tile)
    __half* sV = sK + KT * STRIDE;        // KT x STRIDE (v tile)
    int* sMask = reinterpret_cast<int*>(sV + KT * STRIDE);

    const int tid  = threadIdx.x;
    const int lane = tid & 31;
    const int wid  = tid >> 5;
    const int b     = blockIdx.y;
    const int qbase = blockIdx.x * QT;
    const int wrow  = wid * 16;
    const int quad  = lane >> 2;
    const int qc    = lane & 3;

    const uint32_t sQb = (uint32_t)__cvta_generic_to_shared(sQ);
    const uint32_t sKb = (uint32_t)__cvta_generic_to_shared(sK);
    const uint32_t sVb = (uint32_t)__cvta_generic_to_shared(sV);

    // ldmatrix lane-pattern base addresses (bytes)
    const uint32_t aBase = sQb +
        (uint32_t)(((wrow + (lane & 15)) * STRIDE + ((lane >> 4) << 3)) * 2);
    const uint32_t bBaseK = sKb +
        (uint32_t)(((((lane & 7) + ((lane >> 4) << 3)) * STRIDE) + (((lane >> 3) & 1) << 3)) * 2);
    const uint32_t bBaseW = sKb +
        (uint32_t)(((((lane & 7) + (((lane >> 3) & 1) << 3)) * STRIDE) + ((lane >> 4) << 3)) * 2);
    const uint32_t bBaseV = sVb +
        (uint32_t)(((((lane & 7) + (((lane >> 3) & 1) << 3)) * STRIDE) + ((lane >> 4) << 3)) * 2);

    // ---- load q tile (fp32 -> fp16 in sQ) ----
    {
        const float4* qg = reinterpret_cast<const float4*>(q + ((size_t)b * CLQ + qbase) * CD);
#pragma unroll
        for (int i = 0; i < 32; i++) {
            int e = tid + i * NTHREADS;   // 8192 float4 total
            int row = e >> 6, c4 = e & 63;
            float4 f = qg[row * 64 + c4];
            __half2* d = reinterpret_cast<__half2*>(sQ + row * STRIDE + c4 * 4);
            d[0] = __floats2half2_rn(f.x, f.y);
            d[1] = __floats2half2_rn(f.z, f.w);
        }
    }

    // ---- qw = q @ w (fp16 mma, fp32 acc) ----
    float oacc[32][4];
#pragma unroll
    for (int i = 0; i < 32; i++)
#pragma unroll
        for (int j = 0; j < 4; j++) oacc[i][j] = 0.f;

    for (int wb = 0; wb < 4; wb++) {
        __syncthreads();  // q visible (first iter) / previous chunk consumed
        const float4* wg = reinterpret_cast<const float4*>(w + (size_t)wb * 64 * CD);
#pragma unroll
        for (int i = 0; i < 16; i++) {
            int e = tid + i * NTHREADS;   // 4096 float4 total
            int row = e >> 6, c4 = e & 63;
            float4 f = wg[row * 64 + c4];
            __half2* d = reinterpret_cast<__half2*>(sK + row * STRIDE + c4 * 4);
            d[0] = __floats2half2_rn(f.x, f.y);
            d[1] = __floats2half2_rn(f.z, f.w);
        }
        __syncthreads();
#pragma unroll
        for (int kk = 0; kk < 4; kk++) {
            uint32_t a0, a1, a2, a3;
            ldm4(a0, a1, a2, a3, aBase + (uint32_t)((wb * 64 + kk * 16) * 2));
#pragma unroll
            for (int nt2 = 0; nt2 < 16; nt2++) {
                uint32_t b0, b1, b2, b3;
                ldm4t(b0, b1, b2, b3, bBaseW + (uint32_t)((kk * 16 * STRIDE + nt2 * 16) * 2));
                mma16816(oacc[nt2 * 2],     a0, a1, a2, a3, b0, b1);
                mma16816(oacc[nt2 * 2 + 1], a0, a1, a2, a3, b2, b3);
            }
        }
    }
    __syncthreads();
    // store qw (fp16) into sQ, overwriting q
#pragma unroll
    for (int nt = 0; nt < 32; nt++) {
        int col = nt * 8 + qc * 2;
        *reinterpret_cast<__half2*>(sQ + (wrow + quad) * STRIDE + col) =
            __floats2half2_rn(oacc[nt][0], oacc[nt][1]);
        *reinterpret_cast<__half2*>(sQ + (wrow + quad + 8) * STRIDE + col) =
            __floats2half2_rn(oacc[nt][2], oacc[nt][3]);
    }
    __syncthreads();

    const __half* khg = g_kh + (size_t)b * CLK * CD;
    const __half* vhg = g_vh + (size_t)b * CLK * CD;
    const int* maskg = kidx + (size_t)b * CLK;

    // ---- pass 1: running softmax stats (m, l) per row ----
    float m0 = MINIT, m1 = MINIT, l0 = 0.f, l1 = 0.f;

#pragma unroll 1
    for (int kt = 0; kt < CLK / KT; kt++) {
        const uint4* kg = reinterpret_cast<const uint4*>(khg + (size_t)kt * KT * CD);
#pragma unroll
        for (int i = 0; i < 8; i++) {
            int e = tid + i * NTHREADS;   // 2048 uint4
            int row = e >> 5, c8 = e & 31;
            *reinterpret_cast<uint4*>(sK + row * STRIDE + c8 * 8) = kg[row * 32 + c8];
        }
        if (tid < KT) sMask[tid] = maskg[kt * KT + tid];
        __syncthreads();

        float sacc[8][4];
        compute_S(sacc, aBase, bBaseK);

        float rmax0 = NEG_BIG, rmax1 = NEG_BIG;
#pragma unroll
        for (int nt = 0; nt < 8; nt++) {
            int c0 = nt * 8 + qc * 2;
            float f0 = sMask[c0]     ? sacc[nt][0] * SCALE : NEG_BIG;
            float f1 = sMask[c0 + 1] ? sacc[nt][1] * SCALE : NEG_BIG;
            float f2 = sMask[c0]     ? sacc[nt][2] * SCALE : NEG_BIG;
            float f3 = sMask[c0 + 1] ? sacc[nt][3] * SCALE : NEG_BIG;
            sacc[nt][0] = f0; sacc[nt][1] = f1; sacc[nt][2] = f2; sacc[nt][3] = f3;
            rmax0 = fmaxf(rmax0, fmaxf(f0, f1));
            rmax1 = fmaxf(rmax1, fmaxf(f2, f3));
        }
        rmax0 = fmaxf(rmax0, __shfl_xor_sync(0xffffffffu, rmax0, 1));
        rmax0 = fmaxf(rmax0, __shfl_xor_sync(0xffffffffu, rmax0, 2));
        rmax1 = fmaxf(rmax1, __shfl_xor_sync(0xffffffffu, rmax1, 1));
        rmax1 = fmaxf(rmax1, __shfl_xor_sync(0xffffffffu, rmax1, 2));

        float m0n = fmaxf(m0, rmax0), m1n = fmaxf(m1, rmax1);
        float s0 = 0.f, s1 = 0.f;
#pragma unroll
        for (int nt = 0; nt < 8; nt++) {
            s0 += fast_ex2((sacc[nt][0] - m0n) * LOG2E) + fast_ex2((sacc[nt][1] - m0n) * LOG2E);
            s1 += fast_ex2((sacc[nt][2] - m1n) * LOG2E) + fast_ex2((sacc[nt][3] - m1n) * LOG2E);
        }
        s0 += __shfl_xor_sync(0xffffffffu, s0, 1);
        s0 += __shfl_xor_sync(0xffffffffu, s0, 2);
        s1 += __shfl_xor_sync(0xffffffffu, s1, 1);
        s1 += __shfl_xor_sync(0xffffffffu, s1, 2);

        l0 = l0 * fast_ex2((m0 - m0n) * LOG2E) + s0;
        l1 = l1 * fast_ex2((m1 - m1n) * LOG2E) + s1;
        m0 = m0n; m1 = m1n;
        __syncthreads();
    }

    // ---- pass 2: recompute S, write normalized att, accumulate O = att @ v ----
#pragma unroll
    for (int i = 0; i < 32; i++)
#pragma unroll
        for (int j = 0; j < 4; j++) oacc[i][j] = 0.f;

    const float invl0 = 1.0f / l0, invl1 = 1.0f / l1;
    float* attRow0 = att + ((size_t)b * CLQ + qbase + wrow + quad) * CLK;
    float* attRow1 = attRow0 + (size_t)8 * CLK;

#pragma unroll 1
    for (int kt = 0; kt < CLK / KT; kt++) {
        const uint4* kg = reinterpret_cast<const uint4*>(khg + (size_t)kt * KT * CD);
        const uint4* vg = reinterpret_cast<const uint4*>(vhg + (size_t)kt * KT * CD);
#pragma unroll
        for (int i = 0; i < 8; i++) {
            int e = tid + i * NTHREADS;
            int row = e >> 5, c8 = e & 31;
            *reinterpret_cast<uint4*>(sK + row * STRIDE + c8 * 8) = kg[row * 32 + c8];
            *reinterpret_cast<uint4*>(sV + row * STRIDE + c8 * 8) = vg[row * 32 + c8];
        }
        if (tid < KT) sMask[tid] = maskg[kt * KT + tid];
        __syncthreads();

        float sacc[8][4];
        compute_S(sacc, aBase, bBaseK);

        // softmax-normalize, write att, keep p in sacc
#pragma unroll
        for (int nt = 0; nt < 8; nt++) {
            int c0 = nt * 8 + qc * 2;
            float f0 = sMask[c0]     ? sacc[nt][0] * SCALE : NEG_BIG;
            float f1 = sMask[c0 + 1] ? sacc[nt][1] * SCALE : NEG_BIG;
            float f2 = sMask[c0]     ? sacc[nt][2] * SCALE : NEG_BIG;
            float f3 = sMask[c0 + 1] ? sacc[nt][3] * SCALE : NEG_BIG;
            float p0 = fast_ex2((f0 - m0) * LOG2E) * invl0;
            float p1 = fast_ex2((f1 - m0) * LOG2E) * invl0;
            float p2 = fast_ex2((f2 - m1) * LOG2E) * invl1;
            float p3 = fast_ex2((f3 - m1) * LOG2E) * invl1;
            int col = kt * KT + c0;
            *reinterpret_cast<float2*>(attRow0 + col) = make_float2(p0, p1);
            *reinterpret_cast<float2*>(attRow1 + col) = make_float2(p2, p3);
            sacc[nt][0] = p0; sacc[nt][1] = p1; sacc[nt][2] = p2; sacc[nt][3] = p3;
        }

        // O += P @ V  (P from registers, V via ldmatrix.trans)
#pragma unroll
        for (int kc = 0; kc < 4; kc++) {
            uint32_t a0 = h2u(__floats2half2_rn(sacc[2 * kc][0],     sacc[2 * kc][1]));
            uint32_t a1 = h2u(__floats2half2_rn(sacc[2 * kc][2],     sacc[2 * kc][3]));
            uint32_t a2 = h2u(__floats2half2_rn(sacc[2 * kc + 1][0], sacc[2 * kc + 1][1]));
            uint32_t a3 = h2u(__floats2half2_rn(sacc[2 * kc + 1][2], sacc[2 * kc + 1][3]));
#pragma unroll
            for (int nt2 = 0; nt2 < 16; nt2++) {
                uint32_t b0, b1, b2, b3;
                ldm4t(b0, b1, b2, b3, bBaseV + (uint32_t)((kc * 16 * STRIDE + nt2 * 16) * 2));
                mma16816(oacc[nt2 * 2],     a0, a1, a2, a3, b0, b1);
                mma16816(oacc[nt2 * 2 + 1], a0, a1, a2, a3, b2, b3);
            }
        }
        __syncthreads();
    }

    // ---- write out (already normalized: P was normalized before PV) ----
    float* outRow0 = out + ((size_t)b * CLQ + qbase + wrow + quad) * CD;
    float* outRow1 = outRow0 + 8 * CD;
#pragma unroll
    for (int nt = 0; nt < 32; nt++) {
        int col = nt * 8 + qc * 2;
        *reinterpret_cast<float2*>(outRow0 + col) = make_float2(oacc[nt][0], oacc[nt][1]);
        *reinterpret_cast<float2*>(outRow1 + col) = make_float2(oacc[nt][2], oacc[nt][3]);
    }
}

// ---------------------------------------------------------------------------
// launch
// ---------------------------------------------------------------------------
extern "C" void kernel_launch(void* const* d_in, const int* in_sizes, int n_in,
                              void* d_out, int out_size) {
    const float* q    = (const float*)d_in[0];
    const float* k    = (const float*)d_in[1];
    const float* v    = (const float*)d_in[2];
    const int*   kidx = (const int*)d_in[3];
    const float* w    = (const float*)d_in[4];

    float* out = (float*)d_out;
    float* att = out + (size_t)CB * CLQ * CD;

    size_t n4 = (size_t)CB * CLK * CD / 4;
    convert_kv_kernel<<<(unsigned)((n4 + 255) / 256), 256>>>(k, v);

    size_t smemBytes = (size_t)(QT * STRIDE + 2 * KT * STRIDE) * sizeof(__half) + KT * sizeof(int);
    cudaFuncSetAttribute(attn_kernel, cudaFuncAttributeMaxDynamicSharedMemorySize, (int)smemBytes);

    dim3 grid(CLQ / QT, CB);
    attn_kernel<<<grid, NTHREADS, smemBytes>>>(q, w, kidx, out, att);
}

// round 4
// speedup vs baseline: 1.2268x; 1.2268x over previous
#include <cuda_runtime.h>
#include <cuda_fp16.h>
#include <cstdint>

// Problem constants
constexpr int CB  = 4;
constexpr int CLQ = 4096;
constexpr int CLK = 4096;
constexpr int CD  = 256;

constexpr int QT = 128;       // q rows per CTA
constexpr int KT = 64;        // kv rows per tile
constexpr int NT = CLK / KT;  // 64 kv tiles
constexpr int STRIDE = 264;   // smem row stride in halfs for 256-wide fp16 tiles
constexpr int SSTRIDE = 72;   // smem row stride in floats for 64-wide fp32 S tiles
constexpr int NTHREADS = 256; // 8 warps

constexpr float SCALE   = 0.0625f;              // 256^-0.5
constexpr float NEG_BIG = -1000000000.0f;       // NEG_INF from reference
constexpr float LOG2E   = 1.4426950408889634f;
constexpr float MINIT   = -3.0e38f;

// fp16 copies of k and v (static device scratch; same footprint as round-1 kernel)
__device__ __half g_kh[(size_t)CB * CLK * CD];
__device__ __half g_vh[(size_t)CB * CLK * CD];

// ---------------------------------------------------------------------------
// k/v fp32 -> fp16 conversion
// ---------------------------------------------------------------------------
__global__ void convert_kv_kernel(const float* __restrict__ k, const float* __restrict__ v) {
    size_t i = (size_t)blockIdx.x * blockDim.x + threadIdx.x;
    size_t n4 = (size_t)CB * CLK * CD / 4;
    if (i >= n4) return;
    float4 a = reinterpret_cast<const float4*>(k)[i];
    float4 b = reinterpret_cast<const float4*>(v)[i];
    __half2* kh2 = reinterpret_cast<__half2*>(g_kh);
    __half2* vh2 = reinterpret_cast<__half2*>(g_vh);
    kh2[2 * i]     = __floats2half2_rn(a.x, a.y);
    kh2[2 * i + 1] = __floats2half2_rn(a.z, a.w);
    vh2[2 * i]     = __floats2half2_rn(b.x, b.y);
    vh2[2 * i + 1] = __floats2half2_rn(b.z, b.w);
}

// ---------------------------------------------------------------------------
// helpers
// ---------------------------------------------------------------------------
__device__ __forceinline__ float fast_ex2(float x) {
    float r;
    asm("ex2.approx.ftz.f32 %0, %1;" : "=f"(r) : "f"(x));
    return r;
}
__device__ __forceinline__ void ldm4(uint32_t& r0, uint32_t& r1, uint32_t& r2, uint32_t& r3, uint32_t a) {
    asm volatile("ldmatrix.sync.aligned.m8n8.x4.shared.b16 {%0,%1,%2,%3}, [%4];"
                 : "=r"(r0), "=r"(r1), "=r"(r2), "=r"(r3) : "r"(a));
}
__device__ __forceinline__ void ldm4t(uint32_t& r0, uint32_t& r1, uint32_t& r2, uint32_t& r3, uint32_t a) {
    asm volatile("ldmatrix.sync.aligned.m8n8.x4.trans.shared.b16 {%0,%1,%2,%3}, [%4];"
                 : "=r"(r0), "=r"(r1), "=r"(r2), "=r"(r3) : "r"(a));
}
__device__ __forceinline__ void mma16816(float* c, uint32_t a0, uint32_t a1, uint32_t a2, uint32_t a3,
                                         uint32_t b0, uint32_t b1) {
    asm volatile("mma.sync.aligned.m16n8k16.row.col.f32.f16.f16.f32 "
                 "{%0,%1,%2,%3}, {%4,%5,%6,%7}, {%8,%9}, {%0,%1,%2,%3};"
                 : "+f"(c[0]), "+f"(c[1]), "+f"(c[2]), "+f"(c[3])
                 : "r"(a0), "r"(a1), "r"(a2), "r"(a3), "r"(b0), "r"(b1));
}
__device__ __forceinline__ uint32_t h2u(__half2 h) { return *reinterpret_cast<uint32_t*>(&h); }

__device__ __forceinline__ void cp16(uint32_t dst, const void* src) {
    asm volatile("cp.async.cg.shared.global [%0], [%1], 16;" :: "r"(dst), "l"(src));
}
__device__ __forceinline__ void cp_commit() { asm volatile("cp.async.commit_group;"); }
template <int N>
__device__ __forceinline__ void cp_wait() { asm volatile("cp.async.wait_group %0;" :: "n"(N)); }

// S = qw(regs) @ k^T(smem): 16 rows/warp x 64 kv cols, k-dim 256
__device__ __forceinline__ void compute_S_regs(float (&sacc)[8][4], const uint32_t (&aQ)[16][4],
                                               uint32_t bBase) {
#pragma unroll
    for (int i = 0; i < 8; i++)
#pragma unroll
        for (int j = 0; j < 4; j++) sacc[i][j] = 0.f;
#pragma unroll
    for (int kc = 0; kc < 16; kc++) {
#pragma unroll
        for (int nt2 = 0; nt2 < 4; nt2++) {
            uint32_t b0, b1, b2, b3;
            ldm4(b0, b1, b2, b3, bBase + (uint32_t)((nt2 * 16 * STRIDE + kc * 16) * 2));
            mma16816(sacc[nt2 * 2],     aQ[kc][0], aQ[kc][1], aQ[kc][2], aQ[kc][3], b0, b1);
            mma16816(sacc[nt2 * 2 + 1], aQ[kc][0], aQ[kc][1], aQ[kc][2], aQ[kc][3], b2, b3);
        }
    }
}

// ---------------------------------------------------------------------------
// fused kernel: qw gemm + pass1 (S -> att buffer, m/l) + pass2 (p -> att, PV)
// The att output region doubles as the S scratch: pass 1 stores masked+scaled
// scores there; pass 2 reads them back, overwrites with normalized p.
// grid = (LQ/QT, B), 256 threads
// smem layout (bytes):
//   phase A : sQ [0, 67584)            sW [67584, 101376)
//   pass 1  : kbuf0 [0,33792) kbuf1 [33792,67584) mask [67584, 83968)
//   pass 2  : vbuf0 [0,33792) vbuf1 [33792,67584) sbuf0 [67584,104448) sbuf1 [104448,141312)
// ---------------------------------------------------------------------------
extern __shared__ char smem_raw[];

__global__ void __launch_bounds__(NTHREADS, 1)
attn_kernel(const float* __restrict__ q, const float* __restrict__ w,
            const int* __restrict__ kidx, float* __restrict__ out, float* __restrict__ att) {
    __half* smem_h = reinterpret_cast<__half*>(smem_raw);
    __half* sQ = smem_h;                         // 128 x STRIDE
    __half* sW = smem_h + QT * STRIDE;           // 64 x STRIDE (phase A)
    int*   sMaskF = reinterpret_cast<int*>(smem_raw + 67584);           // 4096 ints (pass 1)
    float* sb[2]  = { reinterpret_cast<float*>(smem_raw + 67584),
                      reinterpret_cast<float*>(smem_raw + 104448) };    // 128 x SSTRIDE (pass 2)

    const int tid  = threadIdx.x;
    const int lane = tid & 31;
    const int wid  = tid >> 5;
    const int b     = blockIdx.y;
    const int qbase = blockIdx.x * QT;
    const int wrow  = wid * 16;
    const int quad  = lane >> 2;
    const int qc    = lane & 3;

    const uint32_t smemB = (uint32_t)__cvta_generic_to_shared(smem_raw);
    const uint32_t sQb = smemB;

    // ldmatrix lane-pattern offsets (bytes, relative to a tile base)
    const uint32_t aPat = (uint32_t)(((wrow + (lane & 15)) * STRIDE + ((lane >> 4) << 3)) * 2);
    const uint32_t bPatK = (uint32_t)(((((lane & 7) + ((lane >> 4) << 3)) * STRIDE) +
                                      (((lane >> 3) & 1) << 3)) * 2);
    const uint32_t bPatT = (uint32_t)(((((lane & 7) + (((lane >> 3) & 1) << 3)) * STRIDE) +
                                      ((lane >> 4) << 3)) * 2);
    const uint32_t kBufB[2] = { smemB, smemB + (uint32_t)(KT * STRIDE * 2) };

    // ---- phase A: load q, compute qw = q @ w ----
    {
        const float4* qg = reinterpret_cast<const float4*>(q + ((size_t)b * CLQ + qbase) * CD);
#pragma unroll
        for (int i = 0; i < 32; i++) {
            int e = tid + i * NTHREADS;
            int row = e >> 6, c4 = e & 63;
            float4 f = qg[row * 64 + c4];
            __half2* d = reinterpret_cast<__half2*>(sQ + row * STRIDE + c4 * 4);
            d[0] = __floats2half2_rn(f.x, f.y);
            d[1] = __floats2half2_rn(f.z, f.w);
        }
    }

    float oacc[32][4];
#pragma unroll
    for (int i = 0; i < 32; i++)
#pragma unroll
        for (int j = 0; j < 4; j++) oacc[i][j] = 0.f;

    const uint32_t bBaseW = smemB + (uint32_t)(QT * STRIDE * 2) + bPatT;
    for (int wb = 0; wb < 4; wb++) {
        __syncthreads();
        const float4* wg = reinterpret_cast<const float4*>(w + (size_t)wb * 64 * CD);
#pragma unroll
        for (int i = 0; i < 16; i++) {
            int e = tid + i * NTHREADS;
            int row = e >> 6, c4 = e & 63;
            float4 f = wg[row * 64 + c4];
            __half2* d = reinterpret_cast<__half2*>(sW + row * STRIDE + c4 * 4);
            d[0] = __floats2half2_rn(f.x, f.y);
            d[1] = __floats2half2_rn(f.z, f.w);
        }
        __syncthreads();
#pragma unroll
        for (int kk = 0; kk < 4; kk++) {
            uint32_t a0, a1, a2, a3;
            ldm4(a0, a1, a2, a3, sQb + aPat + (uint32_t)((wb * 64 + kk * 16) * 2));
#pragma unroll
            for (int nt2 = 0; nt2 < 16; nt2++) {
                uint32_t b0, b1, b2, b3;
                ldm4t(b0, b1, b2, b3, bBaseW + (uint32_t)((kk * 16 * STRIDE + nt2 * 16) * 2));
                mma16816(oacc[nt2 * 2],     a0, a1, a2, a3, b0, b1);
                mma16816(oacc[nt2 * 2 + 1], a0, a1, a2, a3, b2, b3);
            }
        }
    }
    __syncthreads();
    // store qw (fp16) into sQ
#pragma unroll
    for (int nt = 0; nt < 32; nt++) {
        int col = nt * 8 + qc * 2;
        *reinterpret_cast<__half2*>(sQ + (wrow + quad) * STRIDE + col) =
            __floats2half2_rn(oacc[nt][0], oacc[nt][1]);
        *reinterpret_cast<__half2*>(sQ + (wrow + quad + 8) * STRIDE + col) =
            __floats2half2_rn(oacc[nt][2], oacc[nt][3]);
    }
    __syncthreads();

    // ---- extract qw A-fragments into registers (64 regs/warp) ----
    uint32_t aQ[16][4];
#pragma unroll
    for (int kc = 0; kc < 16; kc++)
        ldm4(aQ[kc][0], aQ[kc][1], aQ[kc][2], aQ[kc][3], sQb + aPat + (uint32_t)(kc * 16 * 2));
    __syncthreads();   // sQ region free; pass-1 buffers may overwrite

    const __half* khg = g_kh + (size_t)b * CLK * CD;
    const __half* vhg = g_vh + (size_t)b * CLK * CD;
    const int* maskg = kidx + (size_t)b * CLK;

    // ---- pass 1: S tiles -> att buffer (as scratch), running (m, l) ----
    // load full mask row (4096 ints) once
#pragma unroll
    for (int i = 0; i < 4; i++) {
        int e = tid + i * NTHREADS;
        reinterpret_cast<int4*>(sMaskF)[e] = reinterpret_cast<const int4*>(maskg)[e];
    }

    // k tile async load: 64 rows x 512B = 2048 x 16B
    auto load_k = [&](int kt, int buf) {
        const char* src = reinterpret_cast<const char*>(khg + (size_t)kt * KT * CD);
        uint32_t dstB = kBufB[buf];
#pragma unroll
        for (int i = 0; i < 8; i++) {
            int e = tid + i * NTHREADS;
            int row = e >> 5, c = e & 31;
            cp16(dstB + (uint32_t)(row * (STRIDE * 2) + c * 16), src + row * 512 + c * 16);
        }
    };

    float m0 = MINIT, m1 = MINIT, l0 = 0.f, l1 = 0.f;
    float* attRow0 = att + ((size_t)b * CLQ + qbase + wrow + quad) * CLK;
    float* attRow1 = attRow0 + (size_t)8 * CLK;

    load_k(0, 0);
    cp_commit();

#pragma unroll 1
    for (int kt = 0; kt < NT; kt++) {
        if (kt + 1 < NT) {
            load_k(kt + 1, (kt + 1) & 1);
            cp_commit();
            cp_wait<1>();
        } else {
            cp_wait<0>();
        }
        __syncthreads();

        float sacc[8][4];
        compute_S_regs(sacc, aQ, kBufB[kt & 1] + bPatK);

        float rmax0 = NEG_BIG, rmax1 = NEG_BIG;
#pragma unroll
        for (int nt = 0; nt < 8; nt++) {
            int c0 = kt * KT + nt * 8 + qc * 2;
            float f0 = sMaskF[c0]     ? sacc[nt][0] * SCALE : NEG_BIG;
            float f1 = sMaskF[c0 + 1] ? sacc[nt][1] * SCALE : NEG_BIG;
            float f2 = sMaskF[c0]     ? sacc[nt][2] * SCALE : NEG_BIG;
            float f3 = sMaskF[c0 + 1] ? sacc[nt][3] * SCALE : NEG_BIG;
            sacc[nt][0] = f0; sacc[nt][1] = f1; sacc[nt][2] = f2; sacc[nt][3] = f3;
            rmax0 = fmaxf(rmax0, fmaxf(f0, f1));
            rmax1 = fmaxf(rmax1, fmaxf(f2, f3));
            *reinterpret_cast<float2*>(attRow0 + c0) = make_float2(f0, f1);
            *reinterpret_cast<float2*>(attRow1 + c0) = make_float2(f2, f3);
        }
        rmax0 = fmaxf(rmax0, __shfl_xor_sync(0xffffffffu, rmax0, 1));
        rmax0 = fmaxf(rmax0, __shfl_xor_sync(0xffffffffu, rmax0, 2));
        rmax1 = fmaxf(rmax1, __shfl_xor_sync(0xffffffffu, rmax1, 1));
        rmax1 = fmaxf(rmax1, __shfl_xor_sync(0xffffffffu, rmax1, 2));

        float m0n = fmaxf(m0, rmax0), m1n = fmaxf(m1, rmax1);
        float s0 = 0.f, s1 = 0.f;
#pragma unroll
        for (int nt = 0; nt < 8; nt++) {
            s0 += fast_ex2((sacc[nt][0] - m0n) * LOG2E) + fast_ex2((sacc[nt][1] - m0n) * LOG2E);
            s1 += fast_ex2((sacc[nt][2] - m1n) * LOG2E) + fast_ex2((sacc[nt][3] - m1n) * LOG2E);
        }
        s0 += __shfl_xor_sync(0xffffffffu, s0, 1);
        s0 += __shfl_xor_sync(0xffffffffu, s0, 2);
        s1 += __shfl_xor_sync(0xffffffffu, s1, 1);
        s1 += __shfl_xor_sync(0xffffffffu, s1, 2);

        l0 = l0 * fast_ex2((m0 - m0n) * LOG2E) + s0;
        l1 = l1 * fast_ex2((m1 - m1n) * LOG2E) + s1;
        m0 = m0n; m1 = m1n;
        __syncthreads();
    }

    // ---- pass 2: read S from att, write normalized p back, O = P @ V ----
#pragma unroll
    for (int i = 0; i < 32; i++)
#pragma unroll
        for (int j = 0; j < 4; j++) oacc[i][j] = 0.f;

    const float invl0 = 1.0f / l0, invl1 = 1.0f / l1;

    const uint32_t sBufB[2] = { smemB + 67584u, smemB + 104448u };

    // v tile: 64 rows x 512B; s tile (from att): 128 rows x 256B (stride 288B)
    auto load_vs = [&](int kt, int buf) {
        const char* vsrc = reinterpret_cast<const char*>(vhg + (size_t)kt * KT * CD);
        const char* ssrc = reinterpret_cast<const char*>(
            att + ((size_t)b * CLQ + qbase) * CLK + (size_t)kt * KT);
        uint32_t vdst = kBufB[buf];
        uint32_t sdst = sBufB[buf];
#pragma unroll
        for (int i = 0; i < 8; i++) {
            int e = tid + i * NTHREADS;
            int row = e >> 5, c = e & 31;
            cp16(vdst + (uint32_t)(row * (STRIDE * 2) + c * 16), vsrc + row * 512 + c * 16);
        }
#pragma unroll
        for (int i = 0; i < 8; i++) {
            int e = tid + i * NTHREADS;
            int row = e >> 4, c = e & 15;             // 128 rows x 16 chunks
            cp16(sdst + (uint32_t)(row * (SSTRIDE * 4) + c * 16),
                 ssrc + (size_t)row * CLK * 4 + c * 16);
        }
    };

    load_vs(0, 0);
    cp_commit();

#pragma unroll 1
    for (int kt = 0; kt < NT; kt++) {
        if (kt + 1 < NT) {
            load_vs(kt + 1, (kt + 1) & 1);
            cp_commit();
            cp_wait<1>();
        } else {
            cp_wait<0>();
        }
        __syncthreads();

        const float* sbuf = sb[kt & 1];
        const uint32_t vBase = kBufB[kt & 1] + bPatT;

#pragma unroll
        for (int kc = 0; kc < 4; kc++) {
            int c = kc * 16 + qc * 2;
            float2 v00 = *reinterpret_cast<const float2*>(sbuf + (wrow + quad) * SSTRIDE + c);
            float2 v10 = *reinterpret_cast<const float2*>(sbuf + (wrow + quad + 8) * SSTRIDE + c);
            float2 v01 = *reinterpret_cast<const float2*>(sbuf + (wrow + quad) * SSTRIDE + c + 8);
            float2 v11 = *reinterpret_cast<const float2*>(sbuf + (wrow + quad + 8) * SSTRIDE + c + 8);

            float p00x = fast_ex2((v00.x - m0) * LOG2E) * invl0;
            float p00y = fast_ex2((v00.y - m0) * LOG2E) * invl0;
            float p10x = fast_ex2((v10.x - m1) * LOG2E) * invl1;
            float p10y = fast_ex2((v10.y - m1) * LOG2E) * invl1;
            float p01x = fast_ex2((v01.x - m0) * LOG2E) * invl0;
            float p01y = fast_ex2((v01.y - m0) * LOG2E) * invl0;
            float p11x = fast_ex2((v11.x - m1) * LOG2E) * invl1;
            float p11y = fast_ex2((v11.y - m1) * LOG2E) * invl1;

            int col = kt * KT + c;
            *reinterpret_cast<float2*>(attRow0 + col)     = make_float2(p00x, p00y);
            *reinterpret_cast<float2*>(attRow0 + col + 8) = make_float2(p01x, p01y);
            *reinterpret_cast<float2*>(attRow1 + col)     = make_float2(p10x, p10y);
            *reinterpret_cast<float2*>(attRow1 + col + 8) = make_float2(p11x, p11y);

            uint32_t a0 = h2u(__floats2half2_rn(p00x, p00y));
            uint32_t a1 = h2u(__floats2half2_rn(p10x, p10y));
            uint32_t a2 = h2u(__floats2half2_rn(p01x, p01y));
            uint32_t a3 = h2u(__floats2half2_rn(p11x, p11y));
#pragma unroll
            for (int nt2 = 0; nt2 < 16; nt2++) {
                uint32_t b0, b1, b2, b3;
                ldm4t(b0, b1, b2, b3, vBase + (uint32_t)((kc * 16 * STRIDE + nt2 * 16) * 2));
                mma16816(oacc[nt2 * 2],     a0, a1, a2, a3, b0, b1);
                mma16816(oacc[nt2 * 2 + 1], a0, a1, a2, a3, b2, b3);
            }
        }
        __syncthreads();
    }

    // ---- write out ----
    float* outRow0 = out + ((size_t)b * CLQ + qbase + wrow + quad) * CD;
    float* outRow1 = outRow0 + 8 * CD;
#pragma unroll
    for (int nt = 0; nt < 32; nt++) {
        int col = nt * 8 + qc * 2;
        *reinterpret_cast<float2*>(outRow0 + col) = make_float2(oacc[nt][0], oacc[nt][1]);
        *reinterpret_cast<float2*>(outRow1 + col) = make_float2(oacc[nt][2], oacc[nt][3]);
    }
}

// ---------------------------------------------------------------------------
// launch
// ---------------------------------------------------------------------------
extern "C" void kernel_launch(void* const* d_in, const int* in_sizes, int n_in,
                              void* d_out, int out_size) {
    const float* q    = (const float*)d_in[0];
    const float* k    = (const float*)d_in[1];
    const float* v    = (const float*)d_in[2];
    const int*   kidx = (const int*)d_in[3];
    const float* w    = (const float*)d_in[4];

    float* out = (float*)d_out;
    float* att = out + (size_t)CB * CLQ * CD;

    size_t n4 = (size_t)CB * CLK * CD / 4;
    convert_kv_kernel<<<(unsigned)((n4 + 255) / 256), 256>>>(k, v);

    size_t smemBytes = 141312;  // pass-2 footprint (max of all phases)
    cudaFuncSetAttribute(attn_kernel, cudaFuncAttributeMaxDynamicSharedMemorySize, (int)smemBytes);

    dim3 grid(CLQ / QT, CB);
    attn_kernel<<<grid, NTHREADS, smemBytes>>>(q, w, kidx, out, att);
}